// round 1
// baseline (speedup 1.0000x reference)
#include <cuda_runtime.h>
#include <math.h>

// Problem constants (fixed by the reference)
#define N_NODES 50000
#define N_EDGES 800000
#define F_IN    128
#define HID     64
#define H1      3
#define D1      (H1*HID)   // 192
#define OUT     64
#define LRELU   0.2f

// ---------------- scratch (device globals; no allocation allowed) ----------------
__device__ int      g_is64;
__device__ int      g_src[N_EDGES];
__device__ int      g_dst[N_EDGES];
__device__ float    g_xl1[N_NODES * D1];
__device__ float    g_xr1[N_NODES * D1];
__device__ float    g_acc1[N_NODES * D1];
__device__ float    g_h1[N_NODES * D1];
__device__ float    g_xl2[N_NODES * OUT];
__device__ float    g_xr2[N_NODES * OUT];
__device__ float    g_logits1[N_EDGES * H1];   // logits, then exp() in place
__device__ unsigned g_maxk1[N_NODES * H1];
__device__ float    g_den1[N_NODES * H1];
__device__ float    g_logits2[N_EDGES];
__device__ unsigned g_maxk2[N_NODES];
__device__ float    g_den2[N_NODES];

// ---------------- helpers ----------------
// Order-preserving float -> uint key so plain atomicMax works for fp32 segment-max.
__device__ __forceinline__ unsigned fkey(float f) {
    unsigned u = __float_as_uint(f);
    return (u & 0x80000000u) ? ~u : (u | 0x80000000u);
}
__device__ __forceinline__ float funkey(unsigned k) {
    unsigned u = (k & 0x80000000u) ? (k & 0x7fffffffu) : ~k;
    return __uint_as_float(u);
}
__device__ __forceinline__ float lrelu(float v) { return v > 0.f ? v : LRELU * v; }
__device__ __forceinline__ float elu(float v)   { return v > 0.f ? v : expm1f(v); }

// ---------------- edge_index dtype detection + normalization ----------------
// If the buffer is int64, every odd int32 word (high half) is 0 since values < 50000.
__global__ void detect_kernel(const int* __restrict__ p) {
    int acc = 0;
    for (int i = threadIdx.x; i < 2048; i += blockDim.x) acc |= p[2 * i + 1];
    int any = __syncthreads_or(acc);
    if (threadIdx.x == 0) g_is64 = (any == 0) ? 1 : 0;
}

__global__ void convert_kernel(const int* __restrict__ p) {
    int i = blockIdx.x * blockDim.x + threadIdx.x;
    if (i >= N_EDGES) return;
    if (g_is64) {
        g_src[i] = p[2 * i];
        g_dst[i] = p[2 * N_EDGES + 2 * i];
    } else {
        g_src[i] = p[i];
        g_dst[i] = p[N_EDGES + i];
    }
}

// ---------------- clear scratch (runs every launch; buffers must be re-zeroed) ----
__global__ void clear_kernel(float* __restrict__ out) {
    int stride = gridDim.x * blockDim.x;
    for (int i = blockIdx.x * blockDim.x + threadIdx.x; i < N_NODES * D1; i += stride) {
        g_acc1[i] = 0.f;
        if (i < N_NODES * H1) { g_den1[i] = 0.f; g_maxk1[i] = 0u; }
        if (i < N_NODES)      { g_den2[i] = 0.f; g_maxk2[i] = 0u; }
        if (i < N_NODES * OUT) out[i] = 0.f;
    }
}

// ---------------- SGEMM: C[M,N] = A[M,K] @ B[K,N] + bias[N] ----------------
// Requires K % 16 == 0, N % 64 == 0 (holds: K in {128,192}, N in {192,64}).
__global__ __launch_bounds__(256) void sgemm_bias(
    const float* __restrict__ A, const float* __restrict__ Bm,
    const float* __restrict__ bias, float* __restrict__ C,
    int M, int N, int K)
{
    __shared__ float As[64][16];
    __shared__ float Bs[16][64];
    int tid = threadIdx.x;
    int tx = tid & 15, ty = tid >> 4;
    int row0 = blockIdx.y * 64;
    int col0 = blockIdx.x * 64;
    int aRow = tid >> 2, aCol = (tid & 3) << 2;
    int bRow = tid >> 4, bCol = (tid & 15) << 2;

    float acc[4][4] = {};
    for (int k0 = 0; k0 < K; k0 += 16) {
        float4 av = make_float4(0.f, 0.f, 0.f, 0.f);
        if (row0 + aRow < M)
            av = *(const float4*)(A + (size_t)(row0 + aRow) * K + k0 + aCol);
        *(float4*)(&As[aRow][aCol]) = av;
        float4 bv = *(const float4*)(Bm + (size_t)(k0 + bRow) * N + col0 + bCol);
        *(float4*)(&Bs[bRow][bCol]) = bv;
        __syncthreads();
#pragma unroll
        for (int k = 0; k < 16; k++) {
            float ar[4], br[4];
#pragma unroll
            for (int i = 0; i < 4; i++) ar[i] = As[ty + 16 * i][k];
#pragma unroll
            for (int j = 0; j < 4; j++) br[j] = Bs[k][tx + 16 * j];
#pragma unroll
            for (int i = 0; i < 4; i++)
#pragma unroll
                for (int j = 0; j < 4; j++) acc[i][j] += ar[i] * br[j];
        }
        __syncthreads();
    }
#pragma unroll
    for (int i = 0; i < 4; i++) {
        int r = row0 + ty + 16 * i;
        if (r >= M) continue;
#pragma unroll
        for (int j = 0; j < 4; j++) {
            int c = col0 + tx + 16 * j;
            C[(size_t)r * N + c] = acc[i][j] + bias[c];
        }
    }
}

// ---------------- layer 1 edge kernels (warp per edge; 192 channels) ----------------
__global__ void edge_logits1(const float* __restrict__ ea,
                             const float* __restrict__ We,
                             const float* __restrict__ att)
{
    int w = (blockIdx.x * blockDim.x + threadIdx.x) >> 5;
    int lane = threadIdx.x & 31;
    if (w >= N_EDGES) return;
    int s = g_src[w], d = g_dst[w];
    float a = ea[w];
    const float* xl = g_xl1 + (size_t)s * D1;
    const float* xr = g_xr1 + (size_t)d * D1;
    float p0 = 0.f, p1 = 0.f, p2 = 0.f;
#pragma unroll
    for (int g = 0; g < 6; g++) {
        int ch = lane + 32 * g;
        float v = lrelu(xl[ch] + xr[ch] + a * We[ch]);
        float t = v * att[ch];          // att flattened [H1*HID] = ch index directly
        if (g < 2) p0 += t; else if (g < 4) p1 += t; else p2 += t;
    }
#pragma unroll
    for (int off = 16; off; off >>= 1) {
        p0 += __shfl_xor_sync(0xffffffffu, p0, off);
        p1 += __shfl_xor_sync(0xffffffffu, p1, off);
        p2 += __shfl_xor_sync(0xffffffffu, p2, off);
    }
    if (lane == 0) {
        g_logits1[w * 3 + 0] = p0;
        g_logits1[w * 3 + 1] = p1;
        g_logits1[w * 3 + 2] = p2;
        atomicMax(&g_maxk1[d * 3 + 0], fkey(p0));
        atomicMax(&g_maxk1[d * 3 + 1], fkey(p1));
        atomicMax(&g_maxk1[d * 3 + 2], fkey(p2));
    }
}

__global__ void edge_den1() {
    int e = blockIdx.x * blockDim.x + threadIdx.x;
    if (e >= N_EDGES) return;
    int d = g_dst[e];
#pragma unroll
    for (int h = 0; h < 3; h++) {
        float mx = funkey(g_maxk1[d * 3 + h]);
        float ex = expf(g_logits1[e * 3 + h] - mx);
        g_logits1[e * 3 + h] = ex;               // overwrite logit with exp value
        atomicAdd(&g_den1[d * 3 + h], ex);
    }
}

__global__ void edge_scatter1() {
    int w = (blockIdx.x * blockDim.x + threadIdx.x) >> 5;
    int lane = threadIdx.x & 31;
    if (w >= N_EDGES) return;
    int s = g_src[w], d = g_dst[w];
    float al[3];
#pragma unroll
    for (int h = 0; h < 3; h++)
        al[h] = g_logits1[w * 3 + h] / (g_den1[d * 3 + h] + 1e-16f);
    const float* xl = g_xl1 + (size_t)s * D1;
    float* acc = g_acc1 + (size_t)d * D1;
#pragma unroll
    for (int g = 0; g < 6; g++) {
        int ch = lane + 32 * g;
        atomicAdd(&acc[ch], al[g >> 1] * xl[ch]);
    }
}

__global__ void finalize1(const float* __restrict__ bias) {
    int i = blockIdx.x * blockDim.x + threadIdx.x;
    if (i >= N_NODES * D1) return;
    float v = g_acc1[i] + bias[i % D1];
    g_h1[i] = elu(v);
}

// ---------------- layer 2 edge kernels (warp per edge; 64 channels, 1 head) --------
__global__ void edge_logits2(const float* __restrict__ ea,
                             const float* __restrict__ We,
                             const float* __restrict__ att)
{
    int w = (blockIdx.x * blockDim.x + threadIdx.x) >> 5;
    int lane = threadIdx.x & 31;
    if (w >= N_EDGES) return;
    int s = g_src[w], d = g_dst[w];
    float a = ea[w];
    const float* xl = g_xl2 + (size_t)s * OUT;
    const float* xr = g_xr2 + (size_t)d * OUT;
    float p = 0.f;
#pragma unroll
    for (int g = 0; g < 2; g++) {
        int ch = lane + 32 * g;
        float v = lrelu(xl[ch] + xr[ch] + a * We[ch]);
        p += v * att[ch];
    }
#pragma unroll
    for (int off = 16; off; off >>= 1)
        p += __shfl_xor_sync(0xffffffffu, p, off);
    if (lane == 0) {
        g_logits2[w] = p;
        atomicMax(&g_maxk2[d], fkey(p));
    }
}

__global__ void edge_den2() {
    int e = blockIdx.x * blockDim.x + threadIdx.x;
    if (e >= N_EDGES) return;
    int d = g_dst[e];
    float mx = funkey(g_maxk2[d]);
    float ex = expf(g_logits2[e] - mx);
    g_logits2[e] = ex;
    atomicAdd(&g_den2[d], ex);
}

__global__ void edge_scatter2(float* __restrict__ out) {
    int w = (blockIdx.x * blockDim.x + threadIdx.x) >> 5;
    int lane = threadIdx.x & 31;
    if (w >= N_EDGES) return;
    int s = g_src[w], d = g_dst[w];
    float al = g_logits2[w] / (g_den2[d] + 1e-16f);
    const float* xl = g_xl2 + (size_t)s * OUT;
    float* acc = out + (size_t)d * OUT;
#pragma unroll
    for (int g = 0; g < 2; g++) {
        int ch = lane + 32 * g;
        atomicAdd(&acc[ch], al * xl[ch]);
    }
}

__global__ void finalize2(float* __restrict__ out, const float* __restrict__ bias) {
    int i = blockIdx.x * blockDim.x + threadIdx.x;
    if (i >= N_NODES * OUT) return;
    float v = out[i] + bias[i % OUT];
    out[i] = elu(v);
}

// ---------------- launch ----------------
extern "C" void kernel_launch(void* const* d_in, const int* in_sizes, int n_in,
                              void* d_out, int out_size) {
    const float* x     = (const float*)d_in[0];
    const int*   eidx  = (const int*)d_in[1];   // int32 view; dtype detected on device
    const float* eattr = (const float*)d_in[2];
    const float* Wl1   = (const float*)d_in[3];
    const float* bl1   = (const float*)d_in[4];
    const float* Wr1   = (const float*)d_in[5];
    const float* br1   = (const float*)d_in[6];
    const float* We1   = (const float*)d_in[7];
    const float* att1  = (const float*)d_in[8];
    const float* bias1 = (const float*)d_in[9];
    const float* Wl2   = (const float*)d_in[10];
    const float* bl2   = (const float*)d_in[11];
    const float* Wr2   = (const float*)d_in[12];
    const float* br2   = (const float*)d_in[13];
    const float* We2   = (const float*)d_in[14];
    const float* att2  = (const float*)d_in[15];
    const float* bias2 = (const float*)d_in[16];
    float* out = (float*)d_out;

    // device symbol addresses for scratch used as GEMM outputs/inputs
    // (kernels reference globals directly; for sgemm we need raw pointers)
    static float* p_xl1 = nullptr;
    static float* p_xr1 = nullptr;
    static float* p_h1  = nullptr;
    static float* p_xl2 = nullptr;
    static float* p_xr2 = nullptr;
    if (!p_xl1) {
        cudaGetSymbolAddress((void**)&p_xl1, g_xl1);
        cudaGetSymbolAddress((void**)&p_xr1, g_xr1);
        cudaGetSymbolAddress((void**)&p_h1,  g_h1);
        cudaGetSymbolAddress((void**)&p_xl2, g_xl2);
        cudaGetSymbolAddress((void**)&p_xr2, g_xr2);
    }

    const int EB = (N_EDGES * 32 + 255) / 256;  // warp-per-edge grids
    const int ET = (N_EDGES + 255) / 256;       // thread-per-edge grids

    detect_kernel<<<1, 256>>>(eidx);
    convert_kernel<<<ET, 256>>>(eidx);
    clear_kernel<<<4096, 256>>>(out);

    // layer 1 dense transforms: [50000,128] @ [128,192]
    {
        dim3 grid(D1 / 64, (N_NODES + 63) / 64);
        sgemm_bias<<<grid, 256>>>(x, Wl1, bl1, p_xl1, N_NODES, D1, F_IN);
        sgemm_bias<<<grid, 256>>>(x, Wr1, br1, p_xr1, N_NODES, D1, F_IN);
    }
    edge_logits1<<<EB, 256>>>(eattr, We1, att1);
    edge_den1<<<ET, 256>>>();
    edge_scatter1<<<EB, 256>>>();
    finalize1<<<(N_NODES * D1 + 255) / 256, 256>>>(bias1);

    // layer 2 dense transforms: [50000,192] @ [192,64]
    {
        dim3 grid(OUT / 64, (N_NODES + 63) / 64);
        sgemm_bias<<<grid, 256>>>(p_h1, Wl2, bl2, p_xl2, N_NODES, OUT, D1);
        sgemm_bias<<<grid, 256>>>(p_h1, Wr2, br2, p_xr2, N_NODES, OUT, D1);
    }
    edge_logits2<<<EB, 256>>>(eattr, We2, att2);
    edge_den2<<<ET, 256>>>();
    edge_scatter2<<<EB, 256>>>(out);
    finalize2<<<(N_NODES * OUT + 255) / 256, 256>>>(out, bias2);
}

// round 3
// speedup vs baseline: 1.9103x; 1.9103x over previous
#include <cuda_runtime.h>
#include <math.h>

#define N_NODES 50000
#define N_EDGES 800000
#define F_IN    128
#define HID     64
#define H1      3
#define D1      (H1*HID)        // 192
#define OUT     64
#define LRELU   0.2f
#define NBLK    ((N_NODES + 255) / 256)   // 196

// ---------------- scratch (device globals; no allocation allowed) ----------------
__device__ int   g_is64;
__device__ int   g_src[N_EDGES];
__device__ int   g_dst[N_EDGES];
__device__ int   g_cnt[N_NODES];
__device__ int   g_bsum[256];
__device__ int   g_boff[256];
__device__ int   g_rowoff[N_NODES + 1];
__device__ int   g_cur[N_NODES];
__device__ int   g_esrc[N_EDGES];
__device__ float g_ea[N_EDGES];
__device__ float g_xw1[(size_t)N_NODES * 384];  // [node][xl(192) | xr(192)]
__device__ float g_h1[(size_t)N_NODES * D1];
__device__ float g_xw2[(size_t)N_NODES * 128];  // [node][xl(64) | xr(64)]

// ---------------- helpers ----------------
__device__ __forceinline__ float lrelu(float v) { return v > 0.f ? v : LRELU * v; }
__device__ __forceinline__ float elu(float v)   { return v > 0.f ? v : expm1f(v); }

// ---------------- edge_index dtype detect + normalize ----------------
__global__ void detect_kernel(const int* __restrict__ p) {
    int acc = 0;
    for (int i = threadIdx.x; i < 2048; i += blockDim.x) acc |= p[2 * i + 1];
    int any = __syncthreads_or(acc);
    if (threadIdx.x == 0) g_is64 = (any == 0) ? 1 : 0;
}

__global__ void convert_kernel(const int* __restrict__ p) {
    int i = blockIdx.x * blockDim.x + threadIdx.x;
    if (i >= N_EDGES) return;
    if (g_is64) {
        g_src[i] = p[2 * i];
        g_dst[i] = p[2 * N_EDGES + 2 * i];
    } else {
        g_src[i] = p[i];
        g_dst[i] = p[N_EDGES + i];
    }
}

// ---------------- CSR build: hist -> scan(3 phase) -> scatter ----------------
__global__ void clear_cnt() {
    int i = blockIdx.x * blockDim.x + threadIdx.x;
    if (i < N_NODES) g_cnt[i] = 0;
}

__global__ void hist_kernel() {
    int e = blockIdx.x * blockDim.x + threadIdx.x;
    if (e < N_EDGES) atomicAdd(&g_cnt[g_dst[e]], 1);
}

__global__ void scanA() {   // per-block sums of g_cnt
    __shared__ int sm[256];
    int i = blockIdx.x * 256 + threadIdx.x;
    sm[threadIdx.x] = (i < N_NODES) ? g_cnt[i] : 0;
    __syncthreads();
    for (int off = 128; off; off >>= 1) {
        if (threadIdx.x < off) sm[threadIdx.x] += sm[threadIdx.x + off];
        __syncthreads();
    }
    if (threadIdx.x == 0) g_bsum[blockIdx.x] = sm[0];
}

__global__ void scanB() {   // exclusive scan of block sums (single block)
    __shared__ int sm[256];
    int t = threadIdx.x;
    sm[t] = (t < NBLK) ? g_bsum[t] : 0;
    __syncthreads();
    for (int off = 1; off < 256; off <<= 1) {
        int v = (t >= off) ? sm[t - off] : 0;
        __syncthreads();
        sm[t] += v;
        __syncthreads();
    }
    if (t < NBLK) g_boff[t] = sm[t] - g_bsum[t];  // exclusive
}

__global__ void scanC() {   // local exclusive scan + block offset -> rowoff, cur
    __shared__ int sm[256];
    int t = threadIdx.x;
    int i = blockIdx.x * 256 + t;
    int c = (i < N_NODES) ? g_cnt[i] : 0;
    sm[t] = c;
    __syncthreads();
    for (int off = 1; off < 256; off <<= 1) {
        int v = (t >= off) ? sm[t - off] : 0;
        __syncthreads();
        sm[t] += v;
        __syncthreads();
    }
    if (i < N_NODES) {
        int start = g_boff[blockIdx.x] + sm[t] - c;
        g_rowoff[i] = start;
        g_cur[i] = start;
    }
    if (blockIdx.x == 0 && t == 0) g_rowoff[N_NODES] = N_EDGES;
}

__global__ void scatter_kernel(const float* __restrict__ eattr) {
    int e = blockIdx.x * blockDim.x + threadIdx.x;
    if (e >= N_EDGES) return;
    int d = g_dst[e];
    int pos = atomicAdd(&g_cur[d], 1);
    g_esrc[pos] = g_src[e];
    g_ea[pos]   = eattr[e];
}

// ---------------- fused SGEMM: C[M,2*halfN] = A @ [B1|B2] + [bias1|bias2] ------
// BM=BN=128, BK=8, 256 threads, 8x8 micro-tile, double-buffered smem.
// Requires K%8==0, halfN%64==0.
__global__ __launch_bounds__(256, 2) void sgemm2(
    const float* __restrict__ A,
    const float* __restrict__ B1, const float* __restrict__ B2,
    const float* __restrict__ bias1, const float* __restrict__ bias2,
    float* __restrict__ C, int M, int K, int halfN)
{
    __shared__ float As[2][8][128];
    __shared__ float Bs[2][8][128];
    const int N = 2 * halfN;
    int tid = threadIdx.x;
    int row0 = blockIdx.y * 128, col0 = blockIdx.x * 128;

    int aRow = tid >> 1, aCol = (tid & 1) * 4;
    int bRow = tid >> 5, bCol = (tid & 31) * 4;
    int gcol = col0 + bCol;
    const float* Bsrc = (gcol < halfN) ? B1 : B2;
    int bc = (gcol < halfN) ? gcol : gcol - halfN;

    int tx = tid & 15, ty = tid >> 4;
    float acc[8][8] = {};

    float4 av, bv;
    {   // prologue: tile 0
        int r = row0 + aRow;
        av = (r < M) ? *(const float4*)(A + (size_t)r * K + aCol)
                     : make_float4(0.f, 0.f, 0.f, 0.f);
        bv = *(const float4*)(Bsrc + (size_t)bRow * halfN + bc);
        As[0][aCol + 0][aRow] = av.x; As[0][aCol + 1][aRow] = av.y;
        As[0][aCol + 2][aRow] = av.z; As[0][aCol + 3][aRow] = av.w;
        *(float4*)&Bs[0][bRow][bCol] = bv;
    }
    __syncthreads();

    int nk = K / 8;
    for (int kt = 0; kt < nk; kt++) {
        int buf = kt & 1;
        if (kt + 1 < nk) {      // prefetch next tile to regs
            int k0 = (kt + 1) * 8;
            int r = row0 + aRow;
            av = (r < M) ? *(const float4*)(A + (size_t)r * K + k0 + aCol)
                         : make_float4(0.f, 0.f, 0.f, 0.f);
            bv = *(const float4*)(Bsrc + (size_t)(k0 + bRow) * halfN + bc);
        }
#pragma unroll
        for (int k = 0; k < 8; k++) {
            float4 a0 = *(const float4*)&As[buf][k][ty * 4];
            float4 a1 = *(const float4*)&As[buf][k][ty * 4 + 64];
            float4 b0 = *(const float4*)&Bs[buf][k][tx * 4];
            float4 b1 = *(const float4*)&Bs[buf][k][tx * 4 + 64];
            float ar[8] = {a0.x, a0.y, a0.z, a0.w, a1.x, a1.y, a1.z, a1.w};
            float br[8] = {b0.x, b0.y, b0.z, b0.w, b1.x, b1.y, b1.z, b1.w};
#pragma unroll
            for (int i = 0; i < 8; i++)
#pragma unroll
                for (int j = 0; j < 8; j++) acc[i][j] += ar[i] * br[j];
        }
        if (kt + 1 < nk) {
            int nb = buf ^ 1;
            As[nb][aCol + 0][aRow] = av.x; As[nb][aCol + 1][aRow] = av.y;
            As[nb][aCol + 2][aRow] = av.z; As[nb][aCol + 3][aRow] = av.w;
            *(float4*)&Bs[nb][bRow][bCol] = bv;
        }
        __syncthreads();
    }

    // epilogue: bias + store
    float bsv[8];
#pragma unroll
    for (int j = 0; j < 8; j++) {
        int c = col0 + ((j < 4) ? tx * 4 + j : 64 + tx * 4 + (j - 4));
        bsv[j] = (c < halfN) ? bias1[c] : bias2[c - halfN];
    }
#pragma unroll
    for (int i = 0; i < 8; i++) {
        int r = row0 + ((i < 4) ? ty * 4 + i : 64 + ty * 4 + (i - 4));
        if (r >= M) continue;
        float4 v0 = make_float4(acc[i][0] + bsv[0], acc[i][1] + bsv[1],
                                acc[i][2] + bsv[2], acc[i][3] + bsv[3]);
        float4 v1 = make_float4(acc[i][4] + bsv[4], acc[i][5] + bsv[5],
                                acc[i][6] + bsv[6], acc[i][7] + bsv[7]);
        *(float4*)(C + (size_t)r * N + col0 + tx * 4)      = v0;
        *(float4*)(C + (size_t)r * N + col0 + 64 + tx * 4) = v1;
    }
}

// ---------------- fused GAT layer 1: warp per dst node, online softmax --------
// softmax without max-subtraction (shift-invariant; |logit| << 88).
__global__ __launch_bounds__(256) void gat1_kernel(
    const float* __restrict__ We, const float* __restrict__ att,
    const float* __restrict__ bias)
{
    int node = blockIdx.x * 8 + (threadIdx.x >> 5);
    int lane = threadIdx.x & 31;
    if (node >= N_NODES) return;
    int beg = g_rowoff[node], end = g_rowoff[node + 1];

    float xr[6], Wev[6], attv[6];
    const float* xrp = g_xw1 + (size_t)node * 384 + 192;
#pragma unroll
    for (int g = 0; g < 6; g++) {
        int ch = lane + 32 * g;
        xr[g]   = xrp[ch];
        Wev[g]  = We[ch];
        attv[g] = att[ch];
    }
    float acc[6] = {}, den0 = 0.f, den1 = 0.f, den2 = 0.f;

    int e = beg;
    int s = 0; float a = 0.f;
    if (e < end) { s = g_esrc[e]; a = g_ea[e]; }
    while (e < end) {
        int e2 = e + 1;
        int s2 = 0; float a2 = 0.f;
        if (e2 < end) { s2 = g_esrc[e2]; a2 = g_ea[e2]; }

        const float* xl = g_xw1 + (size_t)s * 384;
        float xlv[6];
        float p0 = 0.f, p1 = 0.f, p2 = 0.f;
#pragma unroll
        for (int g = 0; g < 6; g++) {
            float xv = xl[lane + 32 * g];
            xlv[g] = xv;
            float v = lrelu(xv + xr[g] + a * Wev[g]);
            float t = v * attv[g];
            if (g < 2) p0 += t; else if (g < 4) p1 += t; else p2 += t;
        }
#pragma unroll
        for (int off = 16; off; off >>= 1) {
            p0 += __shfl_xor_sync(0xffffffffu, p0, off);
            p1 += __shfl_xor_sync(0xffffffffu, p1, off);
            p2 += __shfl_xor_sync(0xffffffffu, p2, off);
        }
        float w0 = __expf(p0), w1 = __expf(p1), w2 = __expf(p2);
        den0 += w0; den1 += w1; den2 += w2;
        acc[0] += w0 * xlv[0]; acc[1] += w0 * xlv[1];
        acc[2] += w1 * xlv[2]; acc[3] += w1 * xlv[3];
        acc[4] += w2 * xlv[4]; acc[5] += w2 * xlv[5];

        s = s2; a = a2; e = e2;
    }

    float dg[3] = {den0 + 1e-16f, den1 + 1e-16f, den2 + 1e-16f};
    float* h = g_h1 + (size_t)node * D1;
#pragma unroll
    for (int g = 0; g < 6; g++) {
        int ch = lane + 32 * g;
        float v = acc[g] / dg[g >> 1] + bias[ch];
        h[ch] = elu(v);
    }
}

// ---------------- fused GAT layer 2: warp per dst node, 64 ch, 1 head ---------
__global__ __launch_bounds__(256) void gat2_kernel(
    const float* __restrict__ We, const float* __restrict__ att,
    const float* __restrict__ bias, float* __restrict__ out)
{
    int node = blockIdx.x * 8 + (threadIdx.x >> 5);
    int lane = threadIdx.x & 31;
    if (node >= N_NODES) return;
    int beg = g_rowoff[node], end = g_rowoff[node + 1];

    float xr[2], Wev[2], attv[2];
    const float* xrp = g_xw2 + (size_t)node * 128 + 64;
#pragma unroll
    for (int g = 0; g < 2; g++) {
        int ch = lane + 32 * g;
        xr[g]   = xrp[ch];
        Wev[g]  = We[ch];
        attv[g] = att[ch];
    }
    float acc[2] = {}, den = 0.f;

    int e = beg;
    int s = 0; float a = 0.f;
    if (e < end) { s = g_esrc[e]; a = g_ea[e]; }
    while (e < end) {
        int e2 = e + 1;
        int s2 = 0; float a2 = 0.f;
        if (e2 < end) { s2 = g_esrc[e2]; a2 = g_ea[e2]; }

        const float* xl = g_xw2 + (size_t)s * 128;
        float xlv[2];
        float p = 0.f;
#pragma unroll
        for (int g = 0; g < 2; g++) {
            float xv = xl[lane + 32 * g];
            xlv[g] = xv;
            float v = lrelu(xv + xr[g] + a * Wev[g]);
            p += v * attv[g];
        }
#pragma unroll
        for (int off = 16; off; off >>= 1)
            p += __shfl_xor_sync(0xffffffffu, p, off);
        float w = __expf(p);
        den += w;
        acc[0] += w * xlv[0]; acc[1] += w * xlv[1];

        s = s2; a = a2; e = e2;
    }

    float dinv = den + 1e-16f;
    float* o = out + (size_t)node * OUT;
#pragma unroll
    for (int g = 0; g < 2; g++) {
        int ch = lane + 32 * g;
        float v = acc[g] / dinv + bias[ch];
        o[ch] = elu(v);
    }
}

// ---------------- launch ----------------
extern "C" void kernel_launch(void* const* d_in, const int* in_sizes, int n_in,
                              void* d_out, int out_size) {
    const float* x     = (const float*)d_in[0];
    const int*   eidx  = (const int*)d_in[1];
    const float* eattr = (const float*)d_in[2];
    const float* Wl1   = (const float*)d_in[3];
    const float* bl1   = (const float*)d_in[4];
    const float* Wr1   = (const float*)d_in[5];
    const float* br1   = (const float*)d_in[6];
    const float* We1   = (const float*)d_in[7];
    const float* att1  = (const float*)d_in[8];
    const float* bias1 = (const float*)d_in[9];
    const float* Wl2   = (const float*)d_in[10];
    const float* bl2   = (const float*)d_in[11];
    const float* Wr2   = (const float*)d_in[12];
    const float* br2   = (const float*)d_in[13];
    const float* We2   = (const float*)d_in[14];
    const float* att2  = (const float*)d_in[15];
    const float* bias2 = (const float*)d_in[16];
    float* out = (float*)d_out;

    static float* p_xw1 = nullptr;
    static float* p_h1  = nullptr;
    static float* p_xw2 = nullptr;
    if (!p_xw1) {
        cudaGetSymbolAddress((void**)&p_xw1, g_xw1);
        cudaGetSymbolAddress((void**)&p_h1,  g_h1);
        cudaGetSymbolAddress((void**)&p_xw2, g_xw2);
    }

    const int ET = (N_EDGES + 255) / 256;

    // CSR build
    detect_kernel<<<1, 256>>>(eidx);
    convert_kernel<<<ET, 256>>>(eidx);
    clear_cnt<<<NBLK, 256>>>();
    hist_kernel<<<ET, 256>>>();
    scanA<<<NBLK, 256>>>();
    scanB<<<1, 256>>>();
    scanC<<<NBLK, 256>>>();
    scatter_kernel<<<ET, 256>>>(eattr);

    // layer 1: xw1 = x @ [Wl1|Wr1] + [bl1|br1]   (N = 384)
    {
        dim3 grid(3, (N_NODES + 127) / 128);
        sgemm2<<<grid, 256>>>(x, Wl1, Wr1, bl1, br1, p_xw1, N_NODES, F_IN, D1);
    }
    gat1_kernel<<<(N_NODES + 7) / 8, 256>>>(We1, att1, bias1);

    // layer 2: xw2 = h1 @ [Wl2|Wr2] + [bl2|br2]  (N = 128)
    {
        dim3 grid(1, (N_NODES + 127) / 128);
        sgemm2<<<grid, 256>>>(p_h1, Wl2, Wr2, bl2, br2, p_xw2, N_NODES, D1, OUT);
    }
    gat2_kernel<<<(N_NODES + 7) / 8, 256>>>(We2, att2, bias2, out);
}

// round 5
// speedup vs baseline: 2.1080x; 1.1035x over previous
#include <cuda_runtime.h>
#include <math.h>

#define N_NODES 50000
#define N_EDGES 800000
#define F_IN    128
#define HID     64
#define H1      3
#define D1      (H1*HID)        // 192
#define OUT     64
#define LRELU   0.2f
#define NBLK    ((N_NODES + 255) / 256)   // 196

// ---------------- scratch (device globals; no allocation allowed) ----------------
__device__ int   g_is64;
__device__ int   g_src[N_EDGES];
__device__ int   g_dst[N_EDGES];
__device__ int   g_cnt[N_NODES];
__device__ int   g_bsum[256];
__device__ int   g_boff[256];
__device__ int   g_rowoff[N_NODES + 1];
__device__ int   g_cur[N_NODES];
__device__ int   g_esrc[N_EDGES];
__device__ float g_ea[N_EDGES];
__device__ float g_xw1[(size_t)N_NODES * 384];  // [node][xl(192) | xr(192)]
__device__ float g_h1[(size_t)N_NODES * D1];
__device__ float g_xw2[(size_t)N_NODES * 128];  // [node][xl(64) | xr(64)]

// ---------------- helpers ----------------
__device__ __forceinline__ float lrelu(float v) { return v > 0.f ? v : LRELU * v; }
__device__ __forceinline__ float elu(float v)   { return v > 0.f ? v : expm1f(v); }

// ---------------- edge_index dtype detect ----------------
__global__ void detect_kernel(const int* __restrict__ p) {
    int acc = 0;
    for (int i = threadIdx.x; i < 2048; i += blockDim.x) acc |= p[2 * i + 1];
    int any = __syncthreads_or(acc);
    if (threadIdx.x == 0) g_is64 = (any == 0) ? 1 : 0;
}

__global__ void clear_cnt() {
    int i = blockIdx.x * blockDim.x + threadIdx.x;
    if (i < N_NODES) g_cnt[i] = 0;
}

// convert + histogram in one pass
__global__ void convert_hist(const int* __restrict__ p) {
    int i = blockIdx.x * blockDim.x + threadIdx.x;
    if (i >= N_EDGES) return;
    int s, d;
    if (g_is64) {
        s = p[2 * i];
        d = p[2 * N_EDGES + 2 * i];
    } else {
        s = p[i];
        d = p[N_EDGES + i];
    }
    g_src[i] = s;
    g_dst[i] = d;
    atomicAdd(&g_cnt[d], 1);
}

__global__ void scanA() {   // per-block sums of g_cnt
    __shared__ int sm[256];
    int i = blockIdx.x * 256 + threadIdx.x;
    sm[threadIdx.x] = (i < N_NODES) ? g_cnt[i] : 0;
    __syncthreads();
    for (int off = 128; off; off >>= 1) {
        if (threadIdx.x < off) sm[threadIdx.x] += sm[threadIdx.x + off];
        __syncthreads();
    }
    if (threadIdx.x == 0) g_bsum[blockIdx.x] = sm[0];
}

__global__ void scanB() {   // exclusive scan of block sums (single block)
    __shared__ int sm[256];
    int t = threadIdx.x;
    sm[t] = (t < NBLK) ? g_bsum[t] : 0;
    __syncthreads();
    for (int off = 1; off < 256; off <<= 1) {
        int v = (t >= off) ? sm[t - off] : 0;
        __syncthreads();
        sm[t] += v;
        __syncthreads();
    }
    if (t < NBLK) g_boff[t] = sm[t] - g_bsum[t];  // exclusive
}

__global__ void scanC() {   // local exclusive scan + block offset -> rowoff, cur
    __shared__ int sm[256];
    int t = threadIdx.x;
    int i = blockIdx.x * 256 + t;
    int c = (i < N_NODES) ? g_cnt[i] : 0;
    sm[t] = c;
    __syncthreads();
    for (int off = 1; off < 256; off <<= 1) {
        int v = (t >= off) ? sm[t - off] : 0;
        __syncthreads();
        sm[t] += v;
        __syncthreads();
    }
    if (i < N_NODES) {
        int start = g_boff[blockIdx.x] + sm[t] - c;
        g_rowoff[i] = start;
        g_cur[i] = start;
    }
    if (blockIdx.x == 0 && t == 0) g_rowoff[N_NODES] = N_EDGES;
}

__global__ void scatter_kernel(const float* __restrict__ eattr) {
    int e = blockIdx.x * blockDim.x + threadIdx.x;
    if (e >= N_EDGES) return;
    int d = g_dst[e];
    int pos = atomicAdd(&g_cur[d], 1);
    g_esrc[pos] = g_src[e];
    g_ea[pos]   = eattr[e];
}

// ---------------- SGEMM: C[M,2*halfN] = A @ [B1|B2] + [bias1|bias2] ------------
// BM=BN=128, BK=8, 256 threads, 8x8 micro-tile, double-buffered smem.
__global__ __launch_bounds__(256, 2) void sgemm2(
    const float* __restrict__ A,
    const float* __restrict__ B1, const float* __restrict__ B2,
    const float* __restrict__ bias1, const float* __restrict__ bias2,
    float* __restrict__ C, int M, int K, int halfN)
{
    __shared__ float As[2][8][128];
    __shared__ float Bs[2][8][128];
    const int N = 2 * halfN;
    int tid = threadIdx.x;
    int row0 = blockIdx.y * 128, col0 = blockIdx.x * 128;

    int aRow = tid >> 1, aCol = (tid & 1) * 4;
    int bRow = tid >> 5, bCol = (tid & 31) * 4;
    int gcol = col0 + bCol;
    const float* Bsrc = (gcol < halfN) ? B1 : B2;
    int bc = (gcol < halfN) ? gcol : gcol - halfN;

    int tx = tid & 15, ty = tid >> 4;
    float acc[8][8] = {};

    float4 av, bv;
    {
        int r = row0 + aRow;
        av = (r < M) ? *(const float4*)(A + (size_t)r * K + aCol)
                     : make_float4(0.f, 0.f, 0.f, 0.f);
        bv = *(const float4*)(Bsrc + (size_t)bRow * halfN + bc);
        As[0][aCol + 0][aRow] = av.x; As[0][aCol + 1][aRow] = av.y;
        As[0][aCol + 2][aRow] = av.z; As[0][aCol + 3][aRow] = av.w;
        *(float4*)&Bs[0][bRow][bCol] = bv;
    }
    __syncthreads();

    int nk = K / 8;
    for (int kt = 0; kt < nk; kt++) {
        int buf = kt & 1;
        if (kt + 1 < nk) {
            int k0 = (kt + 1) * 8;
            int r = row0 + aRow;
            av = (r < M) ? *(const float4*)(A + (size_t)r * K + k0 + aCol)
                         : make_float4(0.f, 0.f, 0.f, 0.f);
            bv = *(const float4*)(Bsrc + (size_t)(k0 + bRow) * halfN + bc);
        }
#pragma unroll
        for (int k = 0; k < 8; k++) {
            float4 a0 = *(const float4*)&As[buf][k][ty * 4];
            float4 a1 = *(const float4*)&As[buf][k][ty * 4 + 64];
            float4 b0 = *(const float4*)&Bs[buf][k][tx * 4];
            float4 b1 = *(const float4*)&Bs[buf][k][tx * 4 + 64];
            float ar[8] = {a0.x, a0.y, a0.z, a0.w, a1.x, a1.y, a1.z, a1.w};
            float br[8] = {b0.x, b0.y, b0.z, b0.w, b1.x, b1.y, b1.z, b1.w};
#pragma unroll
            for (int i = 0; i < 8; i++)
#pragma unroll
                for (int j = 0; j < 8; j++) acc[i][j] += ar[i] * br[j];
        }
        if (kt + 1 < nk) {
            int nb = buf ^ 1;
            As[nb][aCol + 0][aRow] = av.x; As[nb][aCol + 1][aRow] = av.y;
            As[nb][aCol + 2][aRow] = av.z; As[nb][aCol + 3][aRow] = av.w;
            *(float4*)&Bs[nb][bRow][bCol] = bv;
        }
        __syncthreads();
    }

    float bsv[8];
#pragma unroll
    for (int j = 0; j < 8; j++) {
        int c = col0 + ((j < 4) ? tx * 4 + j : 64 + tx * 4 + (j - 4));
        bsv[j] = (c < halfN) ? bias1[c] : bias2[c - halfN];
    }
#pragma unroll
    for (int i = 0; i < 8; i++) {
        int r = row0 + ((i < 4) ? ty * 4 + i : 64 + ty * 4 + (i - 4));
        if (r >= M) continue;
        float4 v0 = make_float4(acc[i][0] + bsv[0], acc[i][1] + bsv[1],
                                acc[i][2] + bsv[2], acc[i][3] + bsv[3]);
        float4 v1 = make_float4(acc[i][4] + bsv[4], acc[i][5] + bsv[5],
                                acc[i][6] + bsv[6], acc[i][7] + bsv[7]);
        *(float4*)(C + (size_t)r * N + col0 + tx * 4)      = v0;
        *(float4*)(C + (size_t)r * N + col0 + 64 + tx * 4) = v1;
    }
}

// ---------------- SGEMM half-height: BM=64, BN=128 (for the N=128 GEMM tail) ----
__global__ __launch_bounds__(256) void sgemm2h(
    const float* __restrict__ A,
    const float* __restrict__ B1, const float* __restrict__ B2,
    const float* __restrict__ bias1, const float* __restrict__ bias2,
    float* __restrict__ C, int M, int K, int halfN)
{
    __shared__ float As[2][8][64];
    __shared__ float Bs[2][8][128];
    const int N = 2 * halfN;
    int tid = threadIdx.x;
    int row0 = blockIdx.y * 64, col0 = blockIdx.x * 128;

    int aRow = tid >> 2, aCol = (tid & 3) * 2;
    int bRow = tid >> 5, bCol = (tid & 31) * 4;
    int gcol = col0 + bCol;
    const float* Bsrc = (gcol < halfN) ? B1 : B2;
    int bc = (gcol < halfN) ? gcol : gcol - halfN;

    int tx = tid & 15, ty = tid >> 4;   // ty 0..15
    float acc[4][8] = {};

    float2 av; float4 bv;
    {
        int r = row0 + aRow;
        av = (r < M) ? *(const float2*)(A + (size_t)r * K + aCol)
                     : make_float2(0.f, 0.f);
        bv = *(const float4*)(Bsrc + (size_t)bRow * halfN + bc);
        As[0][aCol + 0][aRow] = av.x; As[0][aCol + 1][aRow] = av.y;
        *(float4*)&Bs[0][bRow][bCol] = bv;
    }
    __syncthreads();

    int nk = K / 8;
    for (int kt = 0; kt < nk; kt++) {
        int buf = kt & 1;
        if (kt + 1 < nk) {
            int k0 = (kt + 1) * 8;
            int r = row0 + aRow;
            av = (r < M) ? *(const float2*)(A + (size_t)r * K + k0 + aCol)
                         : make_float2(0.f, 0.f);
            bv = *(const float4*)(Bsrc + (size_t)(k0 + bRow) * halfN + bc);
        }
#pragma unroll
        for (int k = 0; k < 8; k++) {
            float2 a0 = *(const float2*)&As[buf][k][ty * 2];
            float2 a1 = *(const float2*)&As[buf][k][ty * 2 + 32];
            float4 b0 = *(const float4*)&Bs[buf][k][tx * 4];
            float4 b1 = *(const float4*)&Bs[buf][k][tx * 4 + 64];
            float ar[4] = {a0.x, a0.y, a1.x, a1.y};
            float br[8] = {b0.x, b0.y, b0.z, b0.w, b1.x, b1.y, b1.z, b1.w};
#pragma unroll
            for (int i = 0; i < 4; i++)
#pragma unroll
                for (int j = 0; j < 8; j++) acc[i][j] += ar[i] * br[j];
        }
        if (kt + 1 < nk) {
            int nb = buf ^ 1;
            As[nb][aCol + 0][aRow] = av.x; As[nb][aCol + 1][aRow] = av.y;
            *(float4*)&Bs[nb][bRow][bCol] = bv;
        }
        __syncthreads();
    }

    float bsv[8];
#pragma unroll
    for (int j = 0; j < 8; j++) {
        int c = col0 + ((j < 4) ? tx * 4 + j : 64 + tx * 4 + (j - 4));
        bsv[j] = (c < halfN) ? bias1[c] : bias2[c - halfN];
    }
    const int rofs[4] = {ty * 2, ty * 2 + 1, ty * 2 + 32, ty * 2 + 33};
#pragma unroll
    for (int i = 0; i < 4; i++) {
        int r = row0 + rofs[i];
        if (r >= M) continue;
        float4 v0 = make_float4(acc[i][0] + bsv[0], acc[i][1] + bsv[1],
                                acc[i][2] + bsv[2], acc[i][3] + bsv[3]);
        float4 v1 = make_float4(acc[i][4] + bsv[4], acc[i][5] + bsv[5],
                                acc[i][6] + bsv[6], acc[i][7] + bsv[7]);
        *(float4*)(C + (size_t)r * N + col0 + tx * 4)      = v0;
        *(float4*)(C + (size_t)r * N + col0 + 64 + tx * 4) = v1;
    }
}

// ---------------- fused GAT layer 1: warp/node, 24 lanes x 8 contiguous ch -------
// Channel->lane remap is legal: all ops elementwise except the order-free dot.
// Head h = lane>>3 (lanes 0-7:h0, 8-15:h1, 16-23:h2). Lanes 24-31 idle (compute junk).
__global__ __launch_bounds__(256) void gat1_kernel(
    const float* __restrict__ We, const float* __restrict__ att,
    const float* __restrict__ bias)
{
    int node = blockIdx.x * 8 + (threadIdx.x >> 5);
    int lane = threadIdx.x & 31;
    if (node >= N_NODES) return;
    int beg = g_rowoff[node], end = g_rowoff[node + 1];
    int chb = (lane < 24) ? (lane << 3) : 0;

    const float4* xrp = (const float4*)(g_xw1 + (size_t)node * 384 + 192 + chb);
    float4 xr0 = xrp[0], xr1 = xrp[1];
    float4 We0 = *(const float4*)(We + chb),  We4 = *(const float4*)(We + chb + 4);
    float4 at0 = *(const float4*)(att + chb), at4 = *(const float4*)(att + chb + 4);

    float4 acc0 = make_float4(0.f, 0.f, 0.f, 0.f);
    float4 acc1 = make_float4(0.f, 0.f, 0.f, 0.f);
    float den = 0.f;

    int e = beg, s = 0; float a = 0.f;
    if (e < end) { s = g_esrc[e]; a = g_ea[e]; }
    while (e < end) {
        int e2 = e + 1, s2 = 0; float a2 = 0.f;
        if (e2 < end) { s2 = g_esrc[e2]; a2 = g_ea[e2]; }

        const float4* xlp = (const float4*)(g_xw1 + (size_t)s * 384 + chb);
        float4 x0 = xlp[0], x1 = xlp[1];

        float p;
        p  = at0.x * lrelu(fmaf(a, We0.x, x0.x + xr0.x));
        p += at0.y * lrelu(fmaf(a, We0.y, x0.y + xr0.y));
        p += at0.z * lrelu(fmaf(a, We0.z, x0.z + xr0.z));
        p += at0.w * lrelu(fmaf(a, We0.w, x0.w + xr0.w));
        p += at4.x * lrelu(fmaf(a, We4.x, x1.x + xr1.x));
        p += at4.y * lrelu(fmaf(a, We4.y, x1.y + xr1.y));
        p += at4.z * lrelu(fmaf(a, We4.z, x1.z + xr1.z));
        p += at4.w * lrelu(fmaf(a, We4.w, x1.w + xr1.w));
        // head-group (8 lanes) butterfly
        p += __shfl_xor_sync(0xffffffffu, p, 1);
        p += __shfl_xor_sync(0xffffffffu, p, 2);
        p += __shfl_xor_sync(0xffffffffu, p, 4);
        float w = __expf(p);
        den += w;
        acc0.x = fmaf(w, x0.x, acc0.x); acc0.y = fmaf(w, x0.y, acc0.y);
        acc0.z = fmaf(w, x0.z, acc0.z); acc0.w = fmaf(w, x0.w, acc0.w);
        acc1.x = fmaf(w, x1.x, acc1.x); acc1.y = fmaf(w, x1.y, acc1.y);
        acc1.z = fmaf(w, x1.z, acc1.z); acc1.w = fmaf(w, x1.w, acc1.w);

        s = s2; a = a2; e = e2;
    }

    if (lane < 24) {
        float dinv = 1.f / (den + 1e-16f);
        float4 b0 = *(const float4*)(bias + chb);
        float4 b4 = *(const float4*)(bias + chb + 4);
        float4 o0, o1;
        o0.x = elu(fmaf(acc0.x, dinv, b0.x));
        o0.y = elu(fmaf(acc0.y, dinv, b0.y));
        o0.z = elu(fmaf(acc0.z, dinv, b0.z));
        o0.w = elu(fmaf(acc0.w, dinv, b0.w));
        o1.x = elu(fmaf(acc1.x, dinv, b4.x));
        o1.y = elu(fmaf(acc1.y, dinv, b4.y));
        o1.z = elu(fmaf(acc1.z, dinv, b4.z));
        o1.w = elu(fmaf(acc1.w, dinv, b4.w));
        float4* hp = (float4*)(g_h1 + (size_t)node * D1 + chb);
        hp[0] = o0; hp[1] = o1;
    }
}

// ---------------- fused GAT layer 2: warp/node, 2 edges/warp, 16 lanes x 4 ch ----
__global__ __launch_bounds__(256) void gat2_kernel(
    const float* __restrict__ We, const float* __restrict__ att,
    const float* __restrict__ bias, float* __restrict__ out)
{
    int node = blockIdx.x * 8 + (threadIdx.x >> 5);
    int lane = threadIdx.x & 31;
    if (node >= N_NODES) return;
    int beg = g_rowoff[node], end = g_rowoff[node + 1];
    int half = lane >> 4;
    int chb = (lane & 15) << 2;

    float4 xr  = *(const float4*)(g_xw2 + (size_t)node * 128 + 64 + chb);
    float4 Wev = *(const float4*)(We + chb);
    float4 atv = *(const float4*)(att + chb);

    float4 acc = make_float4(0.f, 0.f, 0.f, 0.f);
    float den = 0.f;

    int base = beg;
    int e = base + half;
    bool valid = (e < end) && (base < end);
    int s = 0; float a = 0.f;
    if (valid) { s = g_esrc[e]; a = g_ea[e]; }
    while (base < end) {
        int base2 = base + 2;
        int e2 = base2 + half;
        bool v2 = (base2 < end) && (e2 < end);
        int s2 = 0; float a2 = 0.f;
        if (v2) { s2 = g_esrc[e2]; a2 = g_ea[e2]; }

        float4 x = *(const float4*)(g_xw2 + (size_t)s * 128 + chb);
        float p;
        p  = atv.x * lrelu(fmaf(a, Wev.x, x.x + xr.x));
        p += atv.y * lrelu(fmaf(a, Wev.y, x.y + xr.y));
        p += atv.z * lrelu(fmaf(a, Wev.z, x.z + xr.z));
        p += atv.w * lrelu(fmaf(a, Wev.w, x.w + xr.w));
        // butterfly within 16-lane half
        p += __shfl_xor_sync(0xffffffffu, p, 1);
        p += __shfl_xor_sync(0xffffffffu, p, 2);
        p += __shfl_xor_sync(0xffffffffu, p, 4);
        p += __shfl_xor_sync(0xffffffffu, p, 8);
        float w = valid ? __expf(p) : 0.f;
        den += w;
        acc.x = fmaf(w, x.x, acc.x); acc.y = fmaf(w, x.y, acc.y);
        acc.z = fmaf(w, x.z, acc.z); acc.w = fmaf(w, x.w, acc.w);

        base = base2; s = s2; a = a2; valid = v2;
    }

    // combine the two halves (same channel lives on lane and lane^16)
    den   += __shfl_xor_sync(0xffffffffu, den,   16);
    acc.x += __shfl_xor_sync(0xffffffffu, acc.x, 16);
    acc.y += __shfl_xor_sync(0xffffffffu, acc.y, 16);
    acc.z += __shfl_xor_sync(0xffffffffu, acc.z, 16);
    acc.w += __shfl_xor_sync(0xffffffffu, acc.w, 16);

    if (half == 0) {
        float dinv = 1.f / (den + 1e-16f);
        float4 bv = *(const float4*)(bias + chb);
        float4 o;
        o.x = elu(fmaf(acc.x, dinv, bv.x));
        o.y = elu(fmaf(acc.y, dinv, bv.y));
        o.z = elu(fmaf(acc.z, dinv, bv.z));
        o.w = elu(fmaf(acc.w, dinv, bv.w));
        *(float4*)(out + (size_t)node * OUT + chb) = o;
    }
}

// ---------------- launch ----------------
extern "C" void kernel_launch(void* const* d_in, const int* in_sizes, int n_in,
                              void* d_out, int out_size) {
    const float* x     = (const float*)d_in[0];
    const int*   eidx  = (const int*)d_in[1];
    const float* eattr = (const float*)d_in[2];
    const float* Wl1   = (const float*)d_in[3];
    const float* bl1   = (const float*)d_in[4];
    const float* Wr1   = (const float*)d_in[5];
    const float* br1   = (const float*)d_in[6];
    const float* We1   = (const float*)d_in[7];
    const float* att1  = (const float*)d_in[8];
    const float* bias1 = (const float*)d_in[9];
    const float* Wl2   = (const float*)d_in[10];
    const float* bl2   = (const float*)d_in[11];
    const float* Wr2   = (const float*)d_in[12];
    const float* br2   = (const float*)d_in[13];
    const float* We2   = (const float*)d_in[14];
    const float* att2  = (const float*)d_in[15];
    const float* bias2 = (const float*)d_in[16];
    float* out = (float*)d_out;

    static float* p_xw1 = nullptr;
    static float* p_h1  = nullptr;
    static float* p_xw2 = nullptr;
    if (!p_xw1) {
        cudaGetSymbolAddress((void**)&p_xw1, g_xw1);
        cudaGetSymbolAddress((void**)&p_h1,  g_h1);
        cudaGetSymbolAddress((void**)&p_xw2, g_xw2);
    }

    const int ET = (N_EDGES + 255) / 256;

    // CSR build
    detect_kernel<<<1, 256>>>(eidx);
    clear_cnt<<<NBLK, 256>>>();
    convert_hist<<<ET, 256>>>(eidx);
    scanA<<<NBLK, 256>>>();
    scanB<<<1, 256>>>();
    scanC<<<NBLK, 256>>>();
    scatter_kernel<<<ET, 256>>>(eattr);

    // layer 1: xw1 = x @ [Wl1|Wr1] + [bl1|br1]   (N = 384)
    {
        dim3 grid(3, (N_NODES + 127) / 128);
        sgemm2<<<grid, 256>>>(x, Wl1, Wr1, bl1, br1, p_xw1, N_NODES, F_IN, D1);
    }
    gat1_kernel<<<(N_NODES + 7) / 8, 256>>>(We1, att1, bias1);

    // layer 2: xw2 = h1 @ [Wl2|Wr2] + [bl2|br2]  (N = 128), BM=64 tiles
    {
        dim3 grid(1, (N_NODES + 63) / 64);
        sgemm2h<<<grid, 256>>>(p_h1, Wl2, Wr2, bl2, br2, p_xw2, N_NODES, D1, OUT);
    }
    gat2_kernel<<<(N_NODES + 7) / 8, 256>>>(We2, att2, bias2, out);
}